// round 1
// baseline (speedup 1.0000x reference)
#include <cuda_runtime.h>
#include <cstdint>
#include <cstddef>

// Problem constants
#define BSZ   16384
#define DM    1024
#define RR    64
#define EE    4
#define LL    3
#define NPAD  320   // 256 (E*R) + 4 gate cols, padded to 5*64 for exact tiling

// ---------------------------------------------------------------------------
// Static device scratch (no allocations allowed in kernel_launch)
// ---------------------------------------------------------------------------
__device__ __align__(16) float g_xbuf[2][(size_t)BSZ * DM];          // ping-pong x_l (128 MB)
__device__ __align__(16) float g_Y[(size_t)BSZ * NPAD];              // GEMM1 output (20 MB)
__device__ __align__(16) float g_w[(size_t)BSZ * EE * RR];           // gate-scaled v2 (16 MB)
__device__ __align__(16) float g_W1[LL][DM * NPAD];                  // packed [V | gate_w | 0]
__device__ __align__(16) float g_W3[LL][EE * RR * DM];               // packed U as [K=(e,r)][D]

// ---------------------------------------------------------------------------
// Weight packing (runs every launch; tiny)
// W1[i][d*NPAD + n]: n in [0,256): V[i,e,d,r] with n=e*64+r; [256,260): gate_w[e,d]; else 0
// ---------------------------------------------------------------------------
__global__ void pack_w1_kernel(const float* __restrict__ V,
                               const float* __restrict__ gw,
                               float* __restrict__ W1) {
    int idx = blockIdx.x * blockDim.x + threadIdx.x;
    const int total = LL * DM * NPAD;
    if (idx >= total) return;
    int i   = idx / (DM * NPAD);
    int rem = idx % (DM * NPAD);
    int d   = rem / NPAD;
    int n   = rem % NPAD;
    float v = 0.f;
    if (n < EE * RR) {
        int e = n >> 6, r = n & 63;
        v = V[(((size_t)i * EE + e) * DM + d) * RR + r];
    } else if (n < EE * RR + EE) {
        v = gw[(size_t)(n - EE * RR) * DM + d];
    }
    W1[idx] = v;
}

// W3[i][k*DM + d] = U[i, e, d, r]  with k = e*64 + r
__global__ void pack_w3_kernel(const float* __restrict__ U,
                               float* __restrict__ W3) {
    int idx = blockIdx.x * blockDim.x + threadIdx.x;
    const int total = LL * EE * RR * DM;
    if (idx >= total) return;
    int i   = idx / (EE * RR * DM);
    int rem = idx % (EE * RR * DM);
    int k   = rem / DM;
    int d   = rem % DM;
    int e   = k >> 6, r = k & 63;
    W3[idx] = U[(((size_t)i * EE + e) * DM + d) * RR + r];
}

// ---------------------------------------------------------------------------
// Register-blocked SGEMM:  C[M,N] = A[M,K] @ B[K,N]
// A row-major ld=K, B row-major ld=N, C ld=N. Exact tiling (no bounds checks).
// EPI: out = xl + x0 * (acc + bias[col])   (fused CrossNet epilogue)
// ---------------------------------------------------------------------------
template <int BM, int BN, int BK, int TM, int TN, bool EPI>
__global__ void __launch_bounds__((BM / TM) * (BN / TN))
sgemm_kernel(const float* __restrict__ A,
             const float* __restrict__ Bm,
             float* __restrict__ Cout,
             const float* __restrict__ xl,
             const float* __restrict__ x0,
             const float* __restrict__ bias,
             int N, int K) {
    constexpr int THREADS = (BM / TM) * (BN / TN);

    __shared__ float As[BK][BM];   // A tile stored transposed
    __shared__ float Bs[BK][BN];

    const int tid  = threadIdx.x;
    const int brow = blockIdx.y;
    const int bcol = blockIdx.x;
    const int tr   = tid / (BN / TN);
    const int tc   = tid % (BN / TN);

    const float* Ablk = A + (size_t)brow * BM * K;
    const float* Bblk = Bm + (size_t)bcol * BN;

    float acc[TM][TN];
#pragma unroll
    for (int i = 0; i < TM; ++i)
#pragma unroll
        for (int j = 0; j < TN; ++j) acc[i][j] = 0.f;

    float rm[TM], rn[TN];

    for (int kt = 0; kt < K; kt += BK) {
        // Load A tile (BM x BK), store transposed into As[BK][BM]
        for (int i = tid * 4; i < BM * BK; i += THREADS * 4) {
            int r = i / BK, c = i % BK;
            float4 v = *reinterpret_cast<const float4*>(Ablk + (size_t)r * K + kt + c);
            As[c + 0][r] = v.x;
            As[c + 1][r] = v.y;
            As[c + 2][r] = v.z;
            As[c + 3][r] = v.w;
        }
        // Load B tile (BK x BN)
        for (int i = tid * 4; i < BK * BN; i += THREADS * 4) {
            int r = i / BN, c = i % BN;
            *reinterpret_cast<float4*>(&Bs[r][c]) =
                *reinterpret_cast<const float4*>(Bblk + (size_t)(kt + r) * N + c);
        }
        __syncthreads();

#pragma unroll
        for (int k = 0; k < BK; ++k) {
#pragma unroll
            for (int i = 0; i < TM; i += 4) {
                float4 v = *reinterpret_cast<const float4*>(&As[k][tr * TM + i]);
                rm[i + 0] = v.x; rm[i + 1] = v.y; rm[i + 2] = v.z; rm[i + 3] = v.w;
            }
#pragma unroll
            for (int j = 0; j < TN; j += 4) {
                float4 v = *reinterpret_cast<const float4*>(&Bs[k][tc * TN + j]);
                rn[j + 0] = v.x; rn[j + 1] = v.y; rn[j + 2] = v.z; rn[j + 3] = v.w;
            }
#pragma unroll
            for (int i = 0; i < TM; ++i)
#pragma unroll
                for (int j = 0; j < TN; ++j)
                    acc[i][j] = fmaf(rm[i], rn[j], acc[i][j]);
        }
        __syncthreads();
    }

    // Store (optionally fused CrossNet epilogue)
#pragma unroll
    for (int i = 0; i < TM; ++i) {
        size_t row = (size_t)brow * BM + tr * TM + i;
#pragma unroll
        for (int j = 0; j < TN; j += 4) {
            size_t col = (size_t)bcol * BN + tc * TN + j;
            size_t off = row * N + col;
            float4 v = make_float4(acc[i][j], acc[i][j + 1], acc[i][j + 2], acc[i][j + 3]);
            if constexpr (EPI) {
                float4 a  = *reinterpret_cast<const float4*>(x0 + off);
                float4 b  = *reinterpret_cast<const float4*>(xl + off);
                float4 bb = *reinterpret_cast<const float4*>(bias + col);
                v.x = fmaf(a.x, v.x + bb.x, b.x);
                v.y = fmaf(a.y, v.y + bb.y, b.y);
                v.z = fmaf(a.z, v.z + bb.z, b.z);
                v.w = fmaf(a.w, v.w + bb.w, b.w);
            }
            *reinterpret_cast<float4*>(Cout + off) = v;
        }
    }
}

// ---------------------------------------------------------------------------
// Mix kernel: per row b
//   vt = tanh(Y[b, 0:256]);  logits = Y[b, 256:260]
//   v2[e,r] = tanh( sum_s C[e,r,s] * vt[e*64+s] )
//   g = softmax(logits);  w[b, e*64+r] = g[e] * v2[e,r]
// C stored in dyn smem transposed: Cs[(e*64+s)*64 + r] = C[e,r,s]  (conflict-free)
// ---------------------------------------------------------------------------
#define MIX_ROWS 32
__global__ void __launch_bounds__(256) mix_kernel(const float* __restrict__ Y,
                                                  const float* __restrict__ Cl,
                                                  float* __restrict__ Wout) {
    extern __shared__ float Cs[];        // EE*RR*RR floats = 64 KB
    __shared__ float vt[EE * RR];
    __shared__ float lg[EE];

    const int tid = threadIdx.x;

    // load + transpose C for this layer
    for (int idx = tid; idx < EE * RR * RR; idx += 256) {
        int e = idx >> 12;
        int rem = idx & 4095;
        int s = rem >> 6;
        int r = rem & 63;
        Cs[idx] = Cl[((size_t)e * RR + r) * RR + s];
    }
    __syncthreads();

    const int e = tid >> 6;
    const int r = tid & 63;
    const float* cp = Cs + e * (RR * RR) + r;

    for (int it = 0; it < MIX_ROWS; ++it) {
        int row = blockIdx.x * MIX_ROWS + it;
        const float* yrow = Y + (size_t)row * NPAD;

        vt[tid] = tanhf(yrow[tid]);
        if (tid < EE) lg[tid] = yrow[EE * RR + tid];
        __syncthreads();

        float acc = 0.f;
#pragma unroll
        for (int s = 0; s < RR; ++s)
            acc = fmaf(cp[s * RR], vt[e * RR + s], acc);
        float v2 = tanhf(acc);

        float m  = fmaxf(fmaxf(lg[0], lg[1]), fmaxf(lg[2], lg[3]));
        float e0 = expf(lg[0] - m), e1 = expf(lg[1] - m);
        float e2 = expf(lg[2] - m), e3 = expf(lg[3] - m);
        float inv = 1.f / (e0 + e1 + e2 + e3);
        float ge  = (e == 0 ? e0 : e == 1 ? e1 : e == 2 ? e2 : e3) * inv;

        Wout[(size_t)row * (EE * RR) + tid] = ge * v2;
        __syncthreads();
    }
}

// ---------------------------------------------------------------------------
// Launch
// Inputs (metadata order): inputs[B,D], U[L,E,D,R], V[L,E,D,R], C[L,E,R,R],
//                          gate_w[E,D], bias[L,D].  Output: x_L [B,D] fp32.
// ---------------------------------------------------------------------------
extern "C" void kernel_launch(void* const* d_in, const int* in_sizes, int n_in,
                              void* d_out, int out_size) {
    const float* x0   = (const float*)d_in[0];
    const float* U    = (const float*)d_in[1];
    const float* V    = (const float*)d_in[2];
    const float* C    = (const float*)d_in[3];
    const float* gw   = (const float*)d_in[4];
    const float* bias = (const float*)d_in[5];
    float* out = (float*)d_out;

    float *xb = nullptr, *Y = nullptr, *W = nullptr, *W1 = nullptr, *W3 = nullptr;
    cudaGetSymbolAddress((void**)&xb, g_xbuf);
    cudaGetSymbolAddress((void**)&Y,  g_Y);
    cudaGetSymbolAddress((void**)&W,  g_w);
    cudaGetSymbolAddress((void**)&W1, g_W1);
    cudaGetSymbolAddress((void**)&W3, g_W3);
    float* xb0 = xb;
    float* xb1 = xb + (size_t)BSZ * DM;

    cudaFuncSetAttribute(mix_kernel, cudaFuncAttributeMaxDynamicSharedMemorySize,
                         EE * RR * RR * (int)sizeof(float));

    // Pack weights (cheap; part of the captured graph)
    {
        int t1 = LL * DM * NPAD;
        pack_w1_kernel<<<(t1 + 255) / 256, 256>>>(V, gw, W1);
        int t3 = LL * EE * RR * DM;
        pack_w3_kernel<<<(t3 + 255) / 256, 256>>>(U, W3);
    }

    const float* xcur = x0;
    float* dsts[LL] = {xb0, xb1, out};

    for (int i = 0; i < LL; ++i) {
        // GEMM1: Y[B,320] = xcur @ W1[i]   (V columns + gate logits, zero-padded)
        sgemm_kernel<128, 64, 16, 8, 4, false>
            <<<dim3(NPAD / 64, BSZ / 128), 256>>>(
                xcur, W1 + (size_t)i * DM * NPAD, Y,
                nullptr, nullptr, nullptr, NPAD, DM);

        // Mix: tanh -> C -> tanh -> softmax gate scaling -> w[B,256]
        mix_kernel<<<BSZ / MIX_ROWS, 256, EE * RR * RR * (int)sizeof(float)>>>(
            Y, C + (size_t)i * EE * RR * RR, W);

        // GEMM2 + epilogue: dst = xcur + x0 * (w @ W3[i] + bias[i])
        sgemm_kernel<128, 128, 16, 8, 8, true>
            <<<dim3(DM / 128, BSZ / 128), 256>>>(
                W, W3 + (size_t)i * EE * RR * DM, dsts[i],
                xcur, x0, bias + (size_t)i * DM, DM, EE * RR);

        xcur = dsts[i];
    }
}

// round 3
// speedup vs baseline: 2.1372x; 2.1372x over previous
#include <cuda_runtime.h>
#include <cuda_bf16.h>
#include <cstdint>
#include <cstddef>

// Problem constants
#define BSZ   16384
#define DM    1024
#define RR    64
#define EE    4
#define LL    3
#define NPAD  320     // 256 V cols + 4 gate cols, padded to 5*64
#define KW    256     // E*R

// ---------------------------------------------------------------------------
// Static device buffers (no allocation allowed)
// ---------------------------------------------------------------------------
__device__ __align__(256) float          g_xf[2][(size_t)BSZ * DM];   // fp32 x_l ping-pong
__device__ __align__(256) __nv_bfloat16  g_xh[(size_t)BSZ * DM];      // bf16 hi of x_l
__device__ __align__(256) __nv_bfloat16  g_xlo[(size_t)BSZ * DM];     // bf16 lo of x_l
__device__ __align__(256) float          g_Y[(size_t)BSZ * NPAD];
__device__ __align__(256) __nv_bfloat16  g_wh[(size_t)BSZ * KW];
__device__ __align__(256) __nv_bfloat16  g_wl[(size_t)BSZ * KW];
__device__ __align__(256) __nv_bfloat16  g_W1h[LL * NPAD * DM];       // [n][d] rows
__device__ __align__(256) __nv_bfloat16  g_W1l[LL * NPAD * DM];
__device__ __align__(256) __nv_bfloat16  g_Uh[LL * DM * KW];          // [d][k] rows
__device__ __align__(256) __nv_bfloat16  g_Ul[LL * DM * KW];

// ---------------------------------------------------------------------------
// PTX helpers (baseline sm_80/sm_90 ISA only — no 'a'-gated features)
// ---------------------------------------------------------------------------
__device__ __forceinline__ uint32_t s2u(const void* p) {
    uint32_t a;
    asm("{ .reg .u64 t; cvta.to.shared.u64 t, %1; cvt.u32.u64 %0, t; }" : "=r"(a) : "l"(p));
    return a;
}
__device__ __forceinline__ void cpasync16(uint32_t dst, const void* src) {
    asm volatile("cp.async.cg.shared.global [%0], [%1], 16;" :: "r"(dst), "l"(src) : "memory");
}
#define CP_COMMIT() asm volatile("cp.async.commit_group;" ::: "memory")
#define CP_WAIT1()  asm volatile("cp.async.wait_group 1;" ::: "memory")

__device__ __forceinline__ void ldsm4(uint32_t* r, uint32_t addr) {
    asm volatile("ldmatrix.sync.aligned.m8n8.x4.shared.b16 {%0,%1,%2,%3}, [%4];"
                 : "=r"(r[0]), "=r"(r[1]), "=r"(r[2]), "=r"(r[3]) : "r"(addr));
}
__device__ __forceinline__ void mma16816(float* c, const uint32_t* a, const uint32_t* b) {
    asm volatile(
        "mma.sync.aligned.m16n8k16.row.col.f32.bf16.bf16.f32 "
        "{%0,%1,%2,%3}, {%4,%5,%6,%7}, {%8,%9}, {%0,%1,%2,%3};"
        : "+f"(c[0]), "+f"(c[1]), "+f"(c[2]), "+f"(c[3])
        : "r"(a[0]), "r"(a[1]), "r"(a[2]), "r"(a[3]), "r"(b[0]), "r"(b[1]));
}

// ---------------------------------------------------------------------------
// bf16x3 warp-MMA GEMM:  D[M,N] = A[M,K] @ B[N,K]^T, fp32 accumulate.
// A = Ah + Al (bf16 hi/lo), B = Bh + Bl; D ~= Ah*Bh + Ah*Bl + Al*Bh.
// BM=128 fixed; 8 warps in 4(M) x (BN/WN)(N) grid, warp tile 32 x WN.
// Smem rows padded to 80 bytes (16B-aligned, conflict-free ldmatrix).
// EPI: out = xprev + x0 * (D + bias); also emits bf16 hi/lo of out.
// ---------------------------------------------------------------------------
template <int BN, int WN, int KTOT, bool EPI>
__global__ void __launch_bounds__(256, 1)
mma_gemm(const __nv_bfloat16* __restrict__ Agh, const __nv_bfloat16* __restrict__ Agl,
         const __nv_bfloat16* __restrict__ Bgh, const __nv_bfloat16* __restrict__ Bgl,
         int bRowOff, float* __restrict__ Cout, int ldc,
         const float* __restrict__ xprev, const float* __restrict__ x0,
         const float* __restrict__ bias,
         __nv_bfloat16* __restrict__ nxh, __nv_bfloat16* __restrict__ nxl)
{
    constexpr int BM  = 128;
    constexpr int WM  = 32;
    constexpr int MF  = WM / 16;        // 2
    constexpr int NF  = WN / 8;         // 4 or 8
    constexpr int KCH = KTOT / 32;
    constexpr int SA  = BM * 80;        // bytes per A tile (hi or lo)
    constexpr int SB  = BN * 80;
    constexpr int SST = 2 * SA + 2 * SB;

    extern __shared__ __align__(128) char smem[];
    const uint32_t sbase = s2u(smem);

    const int tid  = threadIdx.x;
    const int lane = tid & 31;
    const int wid  = tid >> 5;
    const int wm   = wid & 3;           // BM/WM = 4 always
    const int wn   = wid >> 2;
    const int m0   = blockIdx.y * BM;
    const int n0   = bRowOff + blockIdx.x * BN;   // B row offset (incl. layer)
    const int c0   = blockIdx.x * BN;             // output column offset

    const int K = KTOT;

    float acc[MF][NF][4];
#pragma unroll
    for (int i = 0; i < MF; ++i)
#pragma unroll
        for (int j = 0; j < NF; ++j)
#pragma unroll
            for (int p = 0; p < 4; ++p) acc[i][j][p] = 0.f;

    auto load_stage = [&](int st, int kt) {
        const uint32_t base = sbase + st * SST;
        const int kk = kt * 32;
#pragma unroll
        for (int c = tid; c < BM * 4; c += 256) {
            const int row = c >> 2, cc = c & 3;
            const size_t g = (size_t)(m0 + row) * K + kk + cc * 8;
            const uint32_t s = row * 80 + cc * 16;
            cpasync16(base + s,      Agh + g);
            cpasync16(base + SA + s, Agl + g);
        }
#pragma unroll
        for (int c = tid; c < BN * 4; c += 256) {
            const int row = c >> 2, cc = c & 3;
            const size_t g = (size_t)(n0 + row) * K + kk + cc * 8;
            const uint32_t s = row * 80 + cc * 16;
            cpasync16(base + 2 * SA + s,      Bgh + g);
            cpasync16(base + 2 * SA + SB + s, Bgl + g);
        }
    };

    load_stage(0, 0);
    CP_COMMIT();

    for (int kt = 0; kt < KCH; ++kt) {
        const int cur = kt & 1;
        if (kt + 1 < KCH) load_stage(cur ^ 1, kt + 1);
        CP_COMMIT();
        CP_WAIT1();
        __syncthreads();

        const uint32_t sb2 = sbase + cur * SST;
        const int arow  = wm * WM + (lane & 15);
        const int brow  = wn * WN + (lane & 7) + ((lane >> 4) << 3);
        const uint32_t akoff = ((lane >> 4) << 3);
        const uint32_t bkoff = (((lane >> 3) & 1) << 3);

#pragma unroll
        for (int ks = 0; ks < 2; ++ks) {
            uint32_t ah[MF][4], al[MF][4];
#pragma unroll
            for (int mf = 0; mf < MF; ++mf) {
                const uint32_t off = (uint32_t)(arow + mf * 16) * 80 + (akoff + ks * 16) * 2;
                ldsm4(ah[mf], sb2 + off);
                ldsm4(al[mf], sb2 + SA + off);
            }
            uint32_t bh[NF][2], bl[NF][2];
#pragma unroll
            for (int nf2 = 0; nf2 < NF / 2; ++nf2) {
                const uint32_t off = (uint32_t)(brow + nf2 * 16) * 80 + (bkoff + ks * 16) * 2;
                uint32_t t[4];
                ldsm4(t, sb2 + 2 * SA + off);
                bh[2 * nf2][0] = t[0]; bh[2 * nf2][1] = t[1];
                bh[2 * nf2 + 1][0] = t[2]; bh[2 * nf2 + 1][1] = t[3];
                ldsm4(t, sb2 + 2 * SA + SB + off);
                bl[2 * nf2][0] = t[0]; bl[2 * nf2][1] = t[1];
                bl[2 * nf2 + 1][0] = t[2]; bl[2 * nf2 + 1][1] = t[3];
            }
#pragma unroll
            for (int mf = 0; mf < MF; ++mf)
#pragma unroll
                for (int nf = 0; nf < NF; ++nf) {
                    mma16816(acc[mf][nf], ah[mf], bh[nf]);
                    mma16816(acc[mf][nf], ah[mf], bl[nf]);
                    mma16816(acc[mf][nf], al[mf], bh[nf]);
                }
        }
        __syncthreads();
    }

    // ----------------- Epilogue -----------------
#pragma unroll
    for (int mf = 0; mf < MF; ++mf) {
#pragma unroll
        for (int p = 0; p < 2; ++p) {
            const int m = m0 + wm * WM + mf * 16 + (lane >> 2) + p * 8;
#pragma unroll
            for (int nf = 0; nf < NF; ++nf) {
                const int col = c0 + wn * WN + nf * 8 + (lane & 3) * 2;
                const size_t off = (size_t)m * ldc + col;
                float v0 = acc[mf][nf][p * 2];
                float v1 = acc[mf][nf][p * 2 + 1];
                if constexpr (EPI) {
                    const float2 xp = *reinterpret_cast<const float2*>(xprev + off);
                    const float2 xz = *reinterpret_cast<const float2*>(x0 + off);
                    const float2 bb = *reinterpret_cast<const float2*>(bias + col);
                    float o0 = fmaf(xz.x, v0 + bb.x, xp.x);
                    float o1 = fmaf(xz.y, v1 + bb.y, xp.y);
                    *reinterpret_cast<float2*>(Cout + off) = make_float2(o0, o1);
                    __nv_bfloat16 h0 = __float2bfloat16(o0);
                    __nv_bfloat16 h1 = __float2bfloat16(o1);
                    __nv_bfloat162 hp; hp.x = h0; hp.y = h1;
                    *reinterpret_cast<__nv_bfloat162*>(nxh + off) = hp;
                    __nv_bfloat162 lp;
                    lp.x = __float2bfloat16(o0 - __bfloat162float(h0));
                    lp.y = __float2bfloat16(o1 - __bfloat162float(h1));
                    *reinterpret_cast<__nv_bfloat162*>(nxl + off) = lp;
                } else {
                    *reinterpret_cast<float2*>(Cout + off) = make_float2(v0, v1);
                }
            }
        }
    }
}

// ---------------------------------------------------------------------------
// Mix kernel: tanh -> C matvec -> tanh -> softmax gating -> bf16 hi/lo w
// ---------------------------------------------------------------------------
__global__ void __launch_bounds__(256) mix_kernel(const float* __restrict__ Y,
                                                  const float* __restrict__ Cl,
                                                  __nv_bfloat16* __restrict__ Wh,
                                                  __nv_bfloat16* __restrict__ Wl)
{
    extern __shared__ float Cs[];          // 64 KB: Cs[(e*64+s)*64 + r] = C[e,r,s]
    __shared__ float vt[4][EE * RR];
    __shared__ float lg[4][EE];

    const int tid = threadIdx.x;
    for (int idx = tid; idx < EE * RR * RR; idx += 256) {
        int e = idx >> 12, rem = idx & 4095, s = rem >> 6, r = rem & 63;
        Cs[idx] = Cl[((size_t)e * RR + r) * RR + s];
    }
    __syncthreads();

    const int e = tid >> 6;
    const float* cp = Cs + e * (RR * RR) + (tid & 63);
    const int row0 = blockIdx.x * 64;

    for (int it = 0; it < 16; ++it) {
        const int row = row0 + it * 4;
#pragma unroll
        for (int q = 0; q < 4; ++q)
            vt[q][tid] = tanhf(Y[(size_t)(row + q) * NPAD + tid]);
        if (tid < 16)
            lg[tid >> 2][tid & 3] = Y[(size_t)(row + (tid >> 2)) * NPAD + EE * RR + (tid & 3)];
        __syncthreads();

        float a0 = 0.f, a1 = 0.f, a2 = 0.f, a3 = 0.f;
        const float* v0 = &vt[0][e * RR];
        const float* v1 = &vt[1][e * RR];
        const float* v2 = &vt[2][e * RR];
        const float* v3 = &vt[3][e * RR];
#pragma unroll
        for (int s = 0; s < RR; ++s) {
            const float c = cp[s * RR];
            a0 = fmaf(c, v0[s], a0);
            a1 = fmaf(c, v1[s], a1);
            a2 = fmaf(c, v2[s], a2);
            a3 = fmaf(c, v3[s], a3);
        }
        const float tv[4] = {tanhf(a0), tanhf(a1), tanhf(a2), tanhf(a3)};
#pragma unroll
        for (int q = 0; q < 4; ++q) {
            const float l0 = lg[q][0], l1 = lg[q][1], l2 = lg[q][2], l3 = lg[q][3];
            const float mx = fmaxf(fmaxf(l0, l1), fmaxf(l2, l3));
            const float e0 = __expf(l0 - mx), e1 = __expf(l1 - mx);
            const float e2 = __expf(l2 - mx), e3 = __expf(l3 - mx);
            const float inv = 1.f / (e0 + e1 + e2 + e3);
            const float ge = (e == 0 ? e0 : e == 1 ? e1 : e == 2 ? e2 : e3) * inv;
            const float w = ge * tv[q];
            const __nv_bfloat16 h = __float2bfloat16(w);
            Wh[(size_t)(row + q) * KW + tid] = h;
            Wl[(size_t)(row + q) * KW + tid] = __float2bfloat16(w - __bfloat162float(h));
        }
        __syncthreads();
    }
}

// ---------------------------------------------------------------------------
// Conversion + weight packing
// ---------------------------------------------------------------------------
__global__ void conv_kernel(const float* __restrict__ x,
                            __nv_bfloat16* __restrict__ xh,
                            __nv_bfloat16* __restrict__ xl) {
    const size_t i = ((size_t)blockIdx.x * blockDim.x + threadIdx.x) * 4;
    const float4 v = *reinterpret_cast<const float4*>(x + i);
    __nv_bfloat16 h0 = __float2bfloat16(v.x), h1 = __float2bfloat16(v.y);
    __nv_bfloat16 h2 = __float2bfloat16(v.z), h3 = __float2bfloat16(v.w);
    __nv_bfloat162 hp0; hp0.x = h0; hp0.y = h1;
    __nv_bfloat162 hp1; hp1.x = h2; hp1.y = h3;
    *reinterpret_cast<__nv_bfloat162*>(xh + i)     = hp0;
    *reinterpret_cast<__nv_bfloat162*>(xh + i + 2) = hp1;
    __nv_bfloat162 lp0, lp1;
    lp0.x = __float2bfloat16(v.x - __bfloat162float(h0));
    lp0.y = __float2bfloat16(v.y - __bfloat162float(h1));
    lp1.x = __float2bfloat16(v.z - __bfloat162float(h2));
    lp1.y = __float2bfloat16(v.w - __bfloat162float(h3));
    *reinterpret_cast<__nv_bfloat162*>(xl + i)     = lp0;
    *reinterpret_cast<__nv_bfloat162*>(xl + i + 2) = lp1;
}

__global__ void pack_w1_kernel(const float* __restrict__ V, const float* __restrict__ gw,
                               __nv_bfloat16* __restrict__ Wh, __nv_bfloat16* __restrict__ Wl) {
    const int idx = blockIdx.x * blockDim.x + threadIdx.x;
    if (idx >= LL * NPAD * DM) return;
    const int i = idx / (NPAD * DM);
    const int rem = idx % (NPAD * DM);
    const int n = rem / DM, d = rem % DM;
    float v = 0.f;
    if (n < EE * RR)
        v = V[(((size_t)i * EE + (n >> 6)) * DM + d) * RR + (n & 63)];
    else if (n < EE * RR + EE)
        v = gw[(size_t)(n - EE * RR) * DM + d];
    const __nv_bfloat16 h = __float2bfloat16(v);
    Wh[idx] = h;
    Wl[idx] = __float2bfloat16(v - __bfloat162float(h));
}

__global__ void pack_u_kernel(const float* __restrict__ U,
                              __nv_bfloat16* __restrict__ Uh, __nv_bfloat16* __restrict__ Ul) {
    const int idx = blockIdx.x * blockDim.x + threadIdx.x;
    if (idx >= LL * DM * KW) return;
    const int i = idx / (DM * KW);
    const int rem = idx % (DM * KW);
    const int d = rem / KW, k = rem % KW;
    const float v = U[(((size_t)i * EE + (k >> 6)) * DM + d) * RR + (k & 63)];
    const __nv_bfloat16 h = __float2bfloat16(v);
    Uh[idx] = h;
    Ul[idx] = __float2bfloat16(v - __bfloat162float(h));
}

// ---------------------------------------------------------------------------
// Launch
// ---------------------------------------------------------------------------
extern "C" void kernel_launch(void* const* d_in, const int* in_sizes, int n_in,
                              void* d_out, int out_size) {
    const float* x0   = (const float*)d_in[0];
    const float* U    = (const float*)d_in[1];
    const float* V    = (const float*)d_in[2];
    const float* C    = (const float*)d_in[3];
    const float* gw   = (const float*)d_in[4];
    const float* bias = (const float*)d_in[5];
    float* out = (float*)d_out;

    float *xf = nullptr, *Y = nullptr;
    __nv_bfloat16 *xh, *xl, *wh, *wl, *w1h, *w1l, *uh, *ul;
    cudaGetSymbolAddress((void**)&xf,  g_xf);
    cudaGetSymbolAddress((void**)&Y,   g_Y);
    cudaGetSymbolAddress((void**)&xh,  g_xh);
    cudaGetSymbolAddress((void**)&xl,  g_xlo);
    cudaGetSymbolAddress((void**)&wh,  g_wh);
    cudaGetSymbolAddress((void**)&wl,  g_wl);
    cudaGetSymbolAddress((void**)&w1h, g_W1h);
    cudaGetSymbolAddress((void**)&w1l, g_W1l);
    cudaGetSymbolAddress((void**)&uh,  g_Uh);
    cudaGetSymbolAddress((void**)&ul,  g_Ul);
    float* xf0 = xf;
    float* xf1 = xf + (size_t)BSZ * DM;

    // Smem: GEMM1 (BN=64): 2*(2*128*80 + 2*64*80) = 61440
    //       GEMM2 (BN=128): 2*(2*128*80 + 2*128*80) = 81920
    constexpr int SMEM1 = 2 * (2 * 128 * 80 + 2 * 64 * 80);
    constexpr int SMEM2 = 2 * (2 * 128 * 80 + 2 * 128 * 80);
    cudaFuncSetAttribute((const void*)mma_gemm<64, 32, DM, false>,
                         cudaFuncAttributeMaxDynamicSharedMemorySize, SMEM1);
    cudaFuncSetAttribute((const void*)mma_gemm<128, 64, KW, true>,
                         cudaFuncAttributeMaxDynamicSharedMemorySize, SMEM2);
    cudaFuncSetAttribute((const void*)mix_kernel,
                         cudaFuncAttributeMaxDynamicSharedMemorySize, EE * RR * RR * 4);

    // Pack weights + initial x conversion (part of the captured graph)
    pack_w1_kernel<<<(LL * NPAD * DM + 255) / 256, 256>>>(V, gw, w1h, w1l);
    pack_u_kernel<<<(LL * DM * KW + 255) / 256, 256>>>(U, uh, ul);
    conv_kernel<<<(BSZ * DM / 4) / 256, 256>>>(x0, xh, xl);

    const float* xcur = x0;
    float* dsts[LL] = {xf0, xf1, out};

    for (int i = 0; i < LL; ++i) {
        // GEMM1: Y[B,320] = x @ [V|gate]^T   (A = xh/xl, B rows = layer i of W1)
        mma_gemm<64, 32, DM, false><<<dim3(NPAD / 64, BSZ / 128), 256, SMEM1>>>(
            xh, xl, w1h, w1l, i * NPAD,
            Y, NPAD, nullptr, nullptr, nullptr, nullptr, nullptr);

        // Mix: tanh -> C -> tanh -> softmax gates -> bf16 hi/lo w
        mix_kernel<<<BSZ / 64, 256, EE * RR * RR * 4>>>(
            Y, C + (size_t)i * EE * RR * RR, wh, wl);

        // GEMM2 + fused epilogue: dst = xcur + x0*(w @ U^T + bias); emits next xh/xl
        mma_gemm<128, 64, KW, true><<<dim3(DM / 128, BSZ / 128), 256, SMEM2>>>(
            wh, wl, uh, ul, i * DM,
            dsts[i], DM, xcur, x0, bias + (size_t)i * DM, xh, xl);

        xcur = dsts[i];
    }
}